// round 15
// baseline (speedup 1.0000x reference)
#include <cuda_runtime.h>

// Persistent-kernel 2-layer LSTM recurrence (GenCRnn): B=64, S=2048, F=128, H=512.
// 128 co-resident blocks, software grid barrier, weights in SMEM, f32x2 math.

#define NBLK 128
#define NTHR 256
#define BB   64
#define SS   2048
#define FF   128
#define HH   512

typedef unsigned long long ull;

// ---------------- global scratch (device BSS; no allocations) ---------------
// Activation layout (float4 "b-innermost"): element (k, b) lives at float index
//   ((k>>2)*64 + b)*4 + (k&3)   -> lane b coalesced LDG.128 per k-group.
__device__ __align__(16) float g_out[HH * BB];
__device__ __align__(16) float g_h1[2][HH * BB];
__device__ __align__(16) float g_h2[2][HH * BB];
__device__ unsigned g_count = 0;
__device__ unsigned g_sense = 0;

// ---------------- helpers ----------------------------------------------------
__device__ __forceinline__ ull ffma2(ull a, ull b, ull c) {
    ull d;
    asm("fma.rn.f32x2 %0, %1, %2, %3;" : "=l"(d) : "l"(a), "l"(b), "l"(c));
    return d;
}
__device__ __forceinline__ ull pk(float x, float y) {
    ull r;
    asm("mov.b64 %0, {%1, %2};" : "=l"(r) : "f"(x), "f"(y));
    return r;
}
__device__ __forceinline__ float psum(ull a) {
    unsigned lo, hi;
    asm("mov.b64 {%0, %1}, %2;" : "=r"(lo), "=r"(hi) : "l"(a));
    return __uint_as_float(lo) + __uint_as_float(hi);
}
__device__ __forceinline__ float sigm(float x) { return 1.0f / (1.0f + expf(-x)); }

// Grid barrier: sense-reversing, self-resetting. Release fence before arrive,
// acquire fence after observe. Total barriers per launch is EVEN (6146), so
// g_sense/g_count return to 0 -> deterministic across graph replays.
__device__ __forceinline__ void gsync(unsigned* s_sense) {
    __syncthreads();
    if (threadIdx.x == 0) {
        unsigned s = *s_sense;
        __threadfence();                               // release
        unsigned arr = atomicAdd(&g_count, 1u);
        if (arr == NBLK - 1) {
            g_count = 0;
            __threadfence();
            *(volatile unsigned*)&g_sense = s;         // publish
        } else {
            while (*(volatile unsigned*)&g_sense != s) { }
        }
        __threadfence();                               // acquire
        *s_sense = s ^ 1u;
    }
    __syncthreads();
}

// ---------------- SMEM layout (float offsets) --------------------------------
#define OW1  0        // LSTM1 rows: [4u][4gate][1024k]  (k<512: Wih, k>=512: Whh)
#define OW2  16384    // LSTM2 rows: same
#define OWC  32768    // Wcomb: [4u][512k]  (= Wg_row_uu @ W_fc2)
#define OWX  34816    // W_fc1 x-part rows: [4u][128f]
#define OWF  35328    // W_fc2 row `blk`: [512k]
#define OXS  35840    // x_t staging: 64 rows x 33 float4 (pad) = 8448 floats
#define OGP  44288    // gen partials: [4u][64b]
#define OB1  44544    // LSTM1 bias [16]
#define OB2  44560    // LSTM2 bias [16]
#define OBC  44576    // adjusted FC1 bias (Wcomb path) [4]
#define OBA  44580    // raw b_fc1 (t==0 path) [4]
#define OBF  44584    // bfc2[blk] [1]
#define SMEM_FLOATS 44592
#define SMEM_BYTES  (SMEM_FLOATS * 4)

// One LSTM cell for this thread's unit: gates = A·Wih_row + Bv·Whh_row + bias.
__device__ __forceinline__ float lstm_step(
    const float* __restrict__ wsm,      // smem weight base (this block)
    const float4* __restrict__ A4,      // global float4, k 0..511 (ih input)
    const float4* __restrict__ B4,      // global float4, k 0..511 (hh input)
    const float* __restrict__ bias,     // smem [16]
    float& c, int b, int u)
{
    ull a0[4], a1[4];
#pragma unroll
    for (int g = 0; g < 4; g++) { a0[g] = 0ull; a1[g] = 0ull; }
    const float4* w0 = (const float4*)wsm + u * 1024;

#pragma unroll 4
    for (int i = 0; i < 128; i++) {
        float4 v = __ldcg(A4 + i * 64 + b);
        ull vlo = pk(v.x, v.y), vhi = pk(v.z, v.w);
#pragma unroll
        for (int g = 0; g < 4; g++) {
            float4 w = w0[g * 256 + i];
            a0[g] = ffma2(vlo, pk(w.x, w.y), a0[g]);
            a1[g] = ffma2(vhi, pk(w.z, w.w), a1[g]);
        }
    }
#pragma unroll 4
    for (int i = 0; i < 128; i++) {
        float4 v = __ldcg(B4 + i * 64 + b);
        ull vlo = pk(v.x, v.y), vhi = pk(v.z, v.w);
#pragma unroll
        for (int g = 0; g < 4; g++) {
            float4 w = w0[g * 256 + 128 + i];
            a0[g] = ffma2(vlo, pk(w.x, w.y), a0[g]);
            a1[g] = ffma2(vhi, pk(w.z, w.w), a1[g]);
        }
    }
    float pi = psum(a0[0]) + psum(a1[0]) + bias[u * 4 + 0];
    float pf = psum(a0[1]) + psum(a1[1]) + bias[u * 4 + 1];
    float pg = psum(a0[2]) + psum(a1[2]) + bias[u * 4 + 2];
    float po = psum(a0[3]) + psum(a1[3]) + bias[u * 4 + 3];
    float ig = sigm(pi), fg = sigm(pf), gg = tanhf(pg), og = sigm(po);
    float cn = fg * c + ig * gg;
    c = cn;
    return og * tanhf(cn);
}

__global__ void __launch_bounds__(NTHR, 1)
gencrnn_kernel(
    const float* __restrict__ x,     const float* __restrict__ pg0,
    const float* __restrict__ h1in,  const float* __restrict__ c1in,
    const float* __restrict__ h2in,  const float* __restrict__ c2in,
    const float* __restrict__ Wfc1,  const float* __restrict__ bfc1,
    const float* __restrict__ Wih1,  const float* __restrict__ Whh1,
    const float* __restrict__ b1,
    const float* __restrict__ Wih2,  const float* __restrict__ Whh2,
    const float* __restrict__ b2,
    const float* __restrict__ Wfc2,  const float* __restrict__ bfc2,
    float* __restrict__ dout, int write_states)
{
    extern __shared__ float smem[];
    __shared__ unsigned s_sense;
    const int tid = threadIdx.x;
    const int blk = blockIdx.x;
    const int b   = tid & 63;
    const int u   = tid >> 6;
    const int uu  = blk * 4 + u;

    if (tid == 0) s_sense = 1u;

    float4* W1s = (float4*)(smem + OW1);
    float4* W2s = (float4*)(smem + OW2);
    float4* XS4 = (float4*)(smem + OXS);
    float*  GP  = smem + OGP;

    // ---------------- one-time weight load / precompute ----------------------
    // LSTM1 + LSTM2 weight rows for this block's 4 units.
    for (int idx = tid; idx < 4096; idx += NTHR) {
        int lu = idx >> 10, g = (idx >> 8) & 3, i = idx & 255;
        int row = g * 512 + blk * 4 + lu;
        float4 v1 = (i < 128) ? ((const float4*)Wih1)[row * 128 + i]
                              : ((const float4*)Whh1)[row * 128 + (i - 128)];
        float4 v2 = (i < 128) ? ((const float4*)Wih2)[row * 128 + i]
                              : ((const float4*)Whh2)[row * 128 + (i - 128)];
        W1s[idx] = v1;
        W2s[idx] = v2;
    }
    // W_fc1 x-part rows: WX[lu*128 + f]
    for (int idx = tid; idx < 128; idx += NTHR) {  // 128 float4 = 512 floats
        int lu = idx >> 5, i = idx & 31;
        ((float4*)(smem + OWX))[idx] = ((const float4*)Wfc1)[(blk * 4 + lu) * 64 + i];
    }
    // W_fc2 row blk (gen feature)
    for (int idx = tid; idx < 512; idx += NTHR)
        smem[OWF + idx] = Wfc2[blk * 512 + idx];
    // Wcomb[lu][k] = sum_f Wfc1[uu,128+f] * Wfc2[f,k]
    for (int idx = tid; idx < 2048; idx += NTHR) {
        int lu = idx >> 9, k = idx & 511;
        const float* wg = Wfc1 + (blk * 4 + lu) * 256 + 128;
        float s = 0.0f;
        for (int f = 0; f < 128; f++) s += wg[f] * Wfc2[f * 512 + k];
        smem[OWC + idx] = s;
    }
    // biases
    if (tid < 16) {
        int lu = tid >> 2, g = tid & 3;
        smem[OB1 + tid] = b1[g * 512 + blk * 4 + lu];
        smem[OB2 + tid] = b2[g * 512 + blk * 4 + lu];
    }
    if (tid < 4) {
        const float* wg = Wfc1 + (blk * 4 + tid) * 256 + 128;
        float s = 0.0f;
        for (int f = 0; f < 128; f++) s += wg[f] * bfc2[f];
        smem[OBC + tid] = bfc1[blk * 4 + tid] + s;
        smem[OBA + tid] = bfc1[blk * 4 + tid];
    }
    if (tid == 0) smem[OBF] = bfc2[blk];

    // initial h states -> buffer 1 (this block owns k-group i == blk)
    float h1v = h1in[b * HH + uu];
    float h2v = h2in[b * HH + uu];
    __stcg(&g_h1[1][(blk * 64 + b) * 4 + u], h1v);
    __stcg(&g_h2[1][(blk * 64 + b) * 4 + u], h2v);
    float c1 = c1in[b * HH + uu];
    float c2 = c2in[b * HH + uu];

    gsync(&s_sense);   // barrier #1: init visible everywhere

    const float4* wxr = (const float4*)(smem + OWX) + u * 32;
    const float4* wcr = (const float4*)(smem + OWC) + u * 128;
    const float4* wfr = (const float4*)(smem + OWF) + u * 32;

    for (int t = 0; t < SS; t++) {
        const int w  = t & 1;
        const int rb = w ^ 1;
        const float4* h2prev = (const float4*)g_h2[rb];

        // -------- phase A: stage x_t; out = relu(x·Wx + h2prev·Wcomb + b');
        //          also emit gen_{t-1}; (t==0 uses prev_gen0 path) ----------
#pragma unroll
        for (int it = 0; it < 8; it++) {
            int g  = it * NTHR + tid;
            int bb = g >> 5, i = g & 31;
            XS4[bb * 33 + i] = ((const float4*)x)[(size_t)bb * (SS * 32) + (size_t)t * 32 + i];
        }
        __syncthreads();

        ull a0 = 0ull, a1 = 0ull;
        const float4* xr = XS4 + b * 33;
#pragma unroll 8
        for (int i = 0; i < 32; i++) {
            float4 v = xr[i];
            float4 wv = wxr[i];
            a0 = ffma2(pk(v.x, v.y), pk(wv.x, wv.y), a0);
            a1 = ffma2(pk(v.z, v.w), pk(wv.z, wv.w), a1);
        }
        if (t > 0) {
#pragma unroll 4
            for (int i = 0; i < 128; i++) {
                float4 v = __ldcg(h2prev + i * 64 + b);
                float4 wv = wcr[i];
                a0 = ffma2(pk(v.x, v.y), pk(wv.x, wv.y), a0);
                a1 = ffma2(pk(v.z, v.w), pk(wv.z, wv.w), a1);
            }
        }
        float acc = psum(a0) + psum(a1);
        if (t == 0) {
            const float* pgr = pg0 + b * FF;
            const float* wgr = Wfc1 + uu * 256 + 128;
            float s = 0.0f;
            for (int f = 0; f < 128; f++) s += pgr[f] * wgr[f];
            acc += s + smem[OBA + u];
        } else {
            acc += smem[OBC + u];
        }
        __stcg(&g_out[(blk * 64 + b) * 4 + u], fmaxf(acc, 0.0f));

        if (t > 0) {  // gen_{t-1} = h2prev · W_fc2[blk] + bfc2[blk]
            ull q0 = 0ull, q1 = 0ull;
#pragma unroll 4
            for (int i = 0; i < 32; i++) {
                float4 v = __ldcg(h2prev + (u * 32 + i) * 64 + b);
                float4 wv = wfr[i];
                q0 = ffma2(pk(v.x, v.y), pk(wv.x, wv.y), q0);
                q1 = ffma2(pk(v.z, v.w), pk(wv.z, wv.w), q1);
            }
            GP[u * 64 + b] = psum(q0) + psum(q1);
        }
        __syncthreads();
        if (t > 0 && u == 0) {
            float gen = GP[b] + GP[64 + b] + GP[128 + b] + GP[192 + b] + smem[OBF];
            dout[(size_t)b * (SS * FF) + (size_t)(t - 1) * FF + blk] = gen;
        }
        gsync(&s_sense);

        // -------- phase B: LSTM1 ------------------------------------------
        h1v = lstm_step(smem + OW1, (const float4*)g_out,
                        (const float4*)g_h1[rb], smem + OB1, c1, b, u);
        __stcg(&g_h1[w][(blk * 64 + b) * 4 + u], h1v);
        gsync(&s_sense);

        // -------- phase C: LSTM2 ------------------------------------------
        h2v = lstm_step(smem + OW2, (const float4*)g_h1[w],
                        (const float4*)g_h2[rb], smem + OB2, c2, b, u);
        __stcg(&g_h2[w][(blk * 64 + b) * 4 + u], h2v);
        gsync(&s_sense);
    }

    // -------- tail: gen_{S-1} from h2 final (buffer 1), final states --------
    {
        const float4* h2f = (const float4*)g_h2[1];   // (S-1)&1 == 1
        ull q0 = 0ull, q1 = 0ull;
#pragma unroll 4
        for (int i = 0; i < 32; i++) {
            float4 v = __ldcg(h2f + (u * 32 + i) * 64 + b);
            float4 wv = wfr[i];
            q0 = ffma2(pk(v.x, v.y), pk(wv.x, wv.y), q0);
            q1 = ffma2(pk(v.z, v.w), pk(wv.z, wv.w), q1);
        }
        GP[u * 64 + b] = psum(q0) + psum(q1);
        __syncthreads();
        if (u == 0) {
            float gen = GP[b] + GP[64 + b] + GP[128 + b] + GP[192 + b] + smem[OBF];
            dout[(size_t)b * (SS * FF) + (size_t)(SS - 1) * FF + blk] = gen;
        }
    }
    if (write_states) {
        size_t base = (size_t)BB * SS * FF;
        dout[base +              b * HH + uu] = h1v;
        dout[base + 1 * BB * HH + b * HH + uu] = c1;
        dout[base + 2 * BB * HH + b * HH + uu] = h2v;
        dout[base + 3 * BB * HH + b * HH + uu] = c2;
    }

    gsync(&s_sense);   // barrier #6146 (even total -> replay-deterministic)
}

extern "C" void kernel_launch(void* const* d_in, const int* in_sizes, int n_in,
                              void* d_out, int out_size) {
    (void)in_sizes; (void)n_in;
    const float* x    = (const float*)d_in[0];
    const float* pg0  = (const float*)d_in[1];
    const float* h1   = (const float*)d_in[2];
    const float* c1   = (const float*)d_in[3];
    const float* h2   = (const float*)d_in[4];
    const float* c2   = (const float*)d_in[5];
    const float* Wfc1 = (const float*)d_in[6];
    const float* bfc1 = (const float*)d_in[7];
    const float* Wih1 = (const float*)d_in[8];
    const float* Whh1 = (const float*)d_in[9];
    const float* b1   = (const float*)d_in[10];
    const float* Wih2 = (const float*)d_in[11];
    const float* Whh2 = (const float*)d_in[12];
    const float* b2   = (const float*)d_in[13];
    const float* Wfc2 = (const float*)d_in[14];
    const float* bfc2 = (const float*)d_in[15];

    static int smem_set = 0;
    if (!smem_set) {
        cudaFuncSetAttribute(gencrnn_kernel,
                             cudaFuncAttributeMaxDynamicSharedMemorySize, SMEM_BYTES);
        smem_set = 1;
    }
    int write_states = (out_size >= BB * SS * FF + 4 * BB * HH) ? 1 : 0;
    gencrnn_kernel<<<NBLK, NTHR, SMEM_BYTES>>>(
        x, pg0, h1, c1, h2, c2, Wfc1, bfc1, Wih1, Whh1, b1,
        Wih2, Whh2, b2, Wfc2, bfc2, (float*)d_out, write_states);
}

// round 16
// speedup vs baseline: 1.4680x; 1.4680x over previous
#include <cuda_runtime.h>

// Persistent-kernel 2-layer LSTM recurrence (GenCRnn): B=64, S=2048, F=128, H=512.
// R16: K-split (NTHR=512, 16 warps/SM), batched-MLP inner loops, acq/rel barrier.

#define NBLK 128
#define NTHR 512
#define BB   64
#define SS   2048
#define FF   128
#define HH   512

typedef unsigned long long ull;

// ---------------- global scratch (device BSS) --------------------------------
// Activation layout (float4 "b-innermost"): element (k, b) at float index
//   ((k>>2)*64 + b)*4 + (k&3)
__device__ __align__(16) float g_out[HH * BB];
__device__ __align__(16) float g_h1[2][HH * BB];
__device__ __align__(16) float g_h2[2][HH * BB];
__device__ unsigned g_count = 0;
__device__ unsigned g_sense = 0;

// ---------------- helpers ----------------------------------------------------
__device__ __forceinline__ ull ffma2(ull a, ull b, ull c) {
    ull d;
    asm("fma.rn.f32x2 %0, %1, %2, %3;" : "=l"(d) : "l"(a), "l"(b), "l"(c));
    return d;
}
__device__ __forceinline__ ull pk(float x, float y) {
    ull r;
    asm("mov.b64 %0, {%1, %2};" : "=l"(r) : "f"(x), "f"(y));
    return r;
}
__device__ __forceinline__ float psum(ull a) {
    unsigned lo, hi;
    asm("mov.b64 {%0, %1}, %2;" : "=r"(lo), "=r"(hi) : "l"(a));
    return __uint_as_float(lo) + __uint_as_float(hi);
}
__device__ __forceinline__ float sigm(float x) { return 1.0f / (1.0f + __expf(-x)); }

__device__ __forceinline__ unsigned atom_arrive(unsigned* p) {
    unsigned r;
    asm volatile("atom.acq_rel.gpu.global.add.u32 %0, [%1], 1;"
                 : "=r"(r) : "l"(p) : "memory");
    return r;
}
__device__ __forceinline__ unsigned ld_acq(unsigned* p) {
    unsigned r;
    asm volatile("ld.acquire.gpu.global.u32 %0, [%1];" : "=r"(r) : "l"(p) : "memory");
    return r;
}
__device__ __forceinline__ void st_rel(unsigned* p, unsigned v) {
    asm volatile("st.release.gpu.global.u32 [%0], %1;" :: "l"(p), "r"(v) : "memory");
}

// Sense-reversing grid barrier. acq_rel arrive; publisher resets count then
// release-publishes sense; spinners acquire-poll. All cross-block data is .cg
// (L2 coherent), so no L1 invalidation / full membar needed. Even total count
// per launch -> g_sense/g_count return to 0 -> graph-replay deterministic.
__device__ __forceinline__ void gsync(unsigned* s_sense) {
    __syncthreads();
    if (threadIdx.x == 0) {
        unsigned s = *s_sense;
        unsigned arr = atom_arrive(&g_count);
        if (arr == NBLK - 1) {
            g_count = 0;
            st_rel(&g_sense, s);
        } else {
            while (ld_acq(&g_sense) != s) { }
        }
        *s_sense = s ^ 1u;
    }
    __syncthreads();
}

// ---------------- SMEM layout (float offsets) --------------------------------
#define OW1  0        // LSTM1 rows: [4u][4gate][1024k] (k<512: Wih, else Whh)
#define OW2  16384    // LSTM2 rows
#define OWC  32768    // Wcomb: [4u][512k] (= Wfc1 gen-part row @ W_fc2)
#define OWX  34816    // W_fc1 x-part rows: [4u][128f]
#define OWF  35328    // W_fc2 row `blk`: [512k]
#define OXS  35840    // x_t staging: 64 rows x 33 float4 (pad) = 8448 floats
#define OPP  44288    // K-split partials: [4u][64b][4g] = 1024 floats
#define OGP  45312    // gen partials: [8seg][64b] = 512 floats
#define OB1  45824
#define OB2  45840
#define OBC  45856
#define OBA  45860
#define OBF  45864
#define SMEM_FLOATS 45872
#define SMEM_BYTES  (SMEM_FLOATS * 4)

// Half-K LSTM partial: 128 float4 MACs against smem weight rows, batched loads.
__device__ __forceinline__ void lstm_partial(
    const float4* __restrict__ w0,     // smem + u*1024 + ks*128 ; gate stride 256
    const float4* __restrict__ In4,    // global (g_out / g_h1 / g_h2), k-half
    int b, float* __restrict__ p)
{
    ull a0[4], a1[4];
#pragma unroll
    for (int g = 0; g < 4; g++) { a0[g] = 0ull; a1[g] = 0ull; }
#pragma unroll 1
    for (int ii = 0; ii < 128; ii += 8) {
        float4 va[8];
#pragma unroll
        for (int j = 0; j < 8; j++) va[j] = __ldcg(In4 + (ii + j) * 64 + b);
#pragma unroll
        for (int j = 0; j < 8; j++) {
            ull vlo = pk(va[j].x, va[j].y), vhi = pk(va[j].z, va[j].w);
#pragma unroll
            for (int g = 0; g < 4; g++) {
                float4 w = w0[g * 256 + ii + j];
                a0[g] = ffma2(vlo, pk(w.x, w.y), a0[g]);
                a1[g] = ffma2(vhi, pk(w.z, w.w), a1[g]);
            }
        }
    }
#pragma unroll
    for (int g = 0; g < 4; g++) p[g] = psum(a0[g]) + psum(a1[g]);
}

__global__ void __launch_bounds__(NTHR, 1)
gencrnn_kernel(
    const float* __restrict__ x,     const float* __restrict__ pg0,
    const float* __restrict__ h1in,  const float* __restrict__ c1in,
    const float* __restrict__ h2in,  const float* __restrict__ c2in,
    const float* __restrict__ Wfc1,  const float* __restrict__ bfc1,
    const float* __restrict__ Wih1,  const float* __restrict__ Whh1,
    const float* __restrict__ b1,
    const float* __restrict__ Wih2,  const float* __restrict__ Whh2,
    const float* __restrict__ b2,
    const float* __restrict__ Wfc2,  const float* __restrict__ bfc2,
    float* __restrict__ dout, int write_states)
{
    extern __shared__ float smem[];
    __shared__ unsigned s_sense;
    const int tid = threadIdx.x;
    const int blk = blockIdx.x;
    const int b   = tid & 63;          // batch lane
    const int u   = (tid >> 6) & 3;    // local unit
    const int ks  = tid >> 8;          // K-half: 0 = input matrix, 1 = hidden matrix
    const int uu  = blk * 4 + u;

    if (tid == 0) s_sense = 1u;

    float4* W1s = (float4*)(smem + OW1);
    float4* W2s = (float4*)(smem + OW2);
    float4* XS4 = (float4*)(smem + OXS);
    float*  PP  = smem + OPP;
    float*  GP  = smem + OGP;

    // ---------------- one-time weight load / precompute ----------------------
    for (int idx = tid; idx < 4096; idx += NTHR) {
        int lu = idx >> 10, g = (idx >> 8) & 3, i = idx & 255;
        int row = g * 512 + blk * 4 + lu;
        float4 v1 = (i < 128) ? ((const float4*)Wih1)[row * 128 + i]
                              : ((const float4*)Whh1)[row * 128 + (i - 128)];
        float4 v2 = (i < 128) ? ((const float4*)Wih2)[row * 128 + i]
                              : ((const float4*)Whh2)[row * 128 + (i - 128)];
        W1s[idx] = v1;
        W2s[idx] = v2;
    }
    for (int idx = tid; idx < 128; idx += NTHR) {
        int lu = idx >> 5, i = idx & 31;
        ((float4*)(smem + OWX))[idx] = ((const float4*)Wfc1)[(blk * 4 + lu) * 64 + i];
    }
    for (int idx = tid; idx < 512; idx += NTHR)
        smem[OWF + idx] = Wfc2[blk * 512 + idx];
    for (int idx = tid; idx < 2048; idx += NTHR) {
        int lu = idx >> 9, k = idx & 511;
        const float* wg = Wfc1 + (blk * 4 + lu) * 256 + 128;
        float s = 0.0f;
        for (int f = 0; f < 128; f++) s += wg[f] * Wfc2[f * 512 + k];
        smem[OWC + idx] = s;
    }
    if (tid < 16) {
        int lu = tid >> 2, g = tid & 3;
        smem[OB1 + tid] = b1[g * 512 + blk * 4 + lu];
        smem[OB2 + tid] = b2[g * 512 + blk * 4 + lu];
    }
    if (tid < 4) {
        const float* wg = Wfc1 + (blk * 4 + tid) * 256 + 128;
        float s = 0.0f;
        for (int f = 0; f < 128; f++) s += wg[f] * bfc2[f];
        smem[OBC + tid] = bfc1[blk * 4 + tid] + s;
        smem[OBA + tid] = bfc1[blk * 4 + tid];
    }
    if (tid == 0) smem[OBF] = bfc2[blk];

    float h1v = 0.0f, h2v = 0.0f, c1 = 0.0f, c2 = 0.0f;
    if (!ks) {   // ks0 threads own cell state + initial h publication
        h1v = h1in[b * HH + uu];
        h2v = h2in[b * HH + uu];
        c1  = c1in[b * HH + uu];
        c2  = c2in[b * HH + uu];
        __stcg(&g_h1[1][(blk * 64 + b) * 4 + u], h1v);
        __stcg(&g_h2[1][(blk * 64 + b) * 4 + u], h2v);
    }

    gsync(&s_sense);   // barrier #1

    const float4* wxr = (const float4*)(smem + OWX) + u * 32;
    const float4* wcr = (const float4*)(smem + OWC) + u * 128;
    const float4* wf4 = (const float4*)(smem + OWF);

    for (int t = 0; t < SS; t++) {
        const int w  = t & 1;
        const int rb = w ^ 1;
        const float4* h2prev = (const float4*)g_h2[rb];

        // ================= phase A ========================================
        // stage x_t cooperatively (2048 float4 / 512 threads)
#pragma unroll
        for (int it = 0; it < 4; it++) {
            int g2 = it * NTHR + tid;
            int bb = g2 >> 5, i2 = g2 & 31;
            XS4[bb * 33 + i2] =
                ((const float4*)x)[(size_t)bb * (SS * 32) + (size_t)t * 32 + i2];
        }
        __syncthreads();

        ull a0 = 0ull, a1 = 0ull;
        float extra = 0.0f;
        if (!ks) {                                    // x · W_fc1(x-part)
            const float4* xr = XS4 + b * 33;
#pragma unroll 8
            for (int i = 0; i < 32; i++) {
                float4 v = xr[i], wv = wxr[i];
                a0 = ffma2(pk(v.x, v.y), pk(wv.x, wv.y), a0);
                a1 = ffma2(pk(v.z, v.w), pk(wv.z, wv.w), a1);
            }
        }
        if (t > 0) {                                  // h2prev · Wcomb (split 48/80)
            const int i0 = ks ? 48 : 0;
            const int i1 = ks ? 128 : 48;
#pragma unroll 1
            for (int ii = i0; ii < i1; ii += 8) {
                float4 va[8];
#pragma unroll
                for (int j = 0; j < 8; j++) va[j] = __ldcg(h2prev + (ii + j) * 64 + b);
#pragma unroll
                for (int j = 0; j < 8; j++) {
                    float4 wv = wcr[ii + j];
                    a0 = ffma2(pk(va[j].x, va[j].y), pk(wv.x, wv.y), a0);
                    a1 = ffma2(pk(va[j].z, va[j].w), pk(wv.z, wv.w), a1);
                }
            }
        } else if (ks) {                              // t==0: prev_gen0 path
            const float* pgr = pg0 + b * FF;
            const float* wgr = Wfc1 + uu * 256 + 128;
            float s = 0.0f;
            for (int f = 0; f < 128; f++) s += pgr[f] * wgr[f];
            extra = s;
        }
        float part = psum(a0) + psum(a1) + extra;

        // gen_{t-1} partial: 8-way split over (u, ks)
        float gp = 0.0f;
        if (t > 0) {
            const int seg = u * 2 + ks;
            ull q0 = 0ull, q1 = 0ull;
#pragma unroll 4
            for (int i = 0; i < 16; i++) {
                float4 v = __ldcg(h2prev + (seg * 16 + i) * 64 + b);
                float4 wv = wf4[seg * 16 + i];
                q0 = ffma2(pk(v.x, v.y), pk(wv.x, wv.y), q0);
                q1 = ffma2(pk(v.z, v.w), pk(wv.z, wv.w), q1);
            }
            gp = psum(q0) + psum(q1);
        }
        if (ks) PP[u * 64 + b] = part;
        GP[(u * 2 + ks) * 64 + b] = gp;
        __syncthreads();
        if (!ks) {
            float acc = part + PP[u * 64 + b] + (t == 0 ? smem[OBA + u] : smem[OBC + u]);
            __stcg(&g_out[(blk * 64 + b) * 4 + u], fmaxf(acc, 0.0f));
        }
        if (t > 0 && tid < 64) {
            float gen = GP[b] + GP[64 + b] + GP[128 + b] + GP[192 + b]
                      + GP[256 + b] + GP[320 + b] + GP[384 + b] + GP[448 + b]
                      + smem[OBF];
            dout[(size_t)b * (SS * FF) + (size_t)(t - 1) * FF + blk] = gen;
        }
        gsync(&s_sense);

        // ================= phase B: LSTM1 =================================
        {
            float p[4];
            const float4* in = ks ? (const float4*)g_h1[rb] : (const float4*)g_out;
            lstm_partial((const float4*)(smem + OW1) + u * 1024 + ks * 128, in, b, p);
            if (ks) *(float4*)&PP[(u * 64 + b) * 4] = make_float4(p[0], p[1], p[2], p[3]);
            __syncthreads();
            if (!ks) {
                float4 q = *(const float4*)&PP[(u * 64 + b) * 4];
                float ig = sigm(p[0] + q.x + smem[OB1 + u * 4 + 0]);
                float fg = sigm(p[1] + q.y + smem[OB1 + u * 4 + 1]);
                float gg = tanhf(p[2] + q.z + smem[OB1 + u * 4 + 2]);
                float og = sigm(p[3] + q.w + smem[OB1 + u * 4 + 3]);
                c1 = fg * c1 + ig * gg;
                h1v = og * tanhf(c1);
                __stcg(&g_h1[w][(blk * 64 + b) * 4 + u], h1v);
            }
            gsync(&s_sense);
        }

        // ================= phase C: LSTM2 =================================
        {
            float p[4];
            const float4* in = ks ? (const float4*)g_h2[rb] : (const float4*)g_h1[w];
            lstm_partial((const float4*)(smem + OW2) + u * 1024 + ks * 128, in, b, p);
            if (ks) *(float4*)&PP[(u * 64 + b) * 4] = make_float4(p[0], p[1], p[2], p[3]);
            __syncthreads();
            if (!ks) {
                float4 q = *(const float4*)&PP[(u * 64 + b) * 4];
                float ig = sigm(p[0] + q.x + smem[OB2 + u * 4 + 0]);
                float fg = sigm(p[1] + q.y + smem[OB2 + u * 4 + 1]);
                float gg = tanhf(p[2] + q.z + smem[OB2 + u * 4 + 2]);
                float og = sigm(p[3] + q.w + smem[OB2 + u * 4 + 3]);
                c2 = fg * c2 + ig * gg;
                h2v = og * tanhf(c2);
                __stcg(&g_h2[w][(blk * 64 + b) * 4 + u], h2v);
            }
            gsync(&s_sense);
        }
    }

    // -------- tail: gen_{S-1} from final h2 (buffer 1) ----------------------
    {
        const float4* h2f = (const float4*)g_h2[1];
        const int seg = u * 2 + ks;
        ull q0 = 0ull, q1 = 0ull;
#pragma unroll 4
        for (int i = 0; i < 16; i++) {
            float4 v = __ldcg(h2f + (seg * 16 + i) * 64 + b);
            float4 wv = wf4[seg * 16 + i];
            q0 = ffma2(pk(v.x, v.y), pk(wv.x, wv.y), q0);
            q1 = ffma2(pk(v.z, v.w), pk(wv.z, wv.w), q1);
        }
        GP[seg * 64 + b] = psum(q0) + psum(q1);
        __syncthreads();
        if (tid < 64) {
            float gen = GP[b] + GP[64 + b] + GP[128 + b] + GP[192 + b]
                      + GP[256 + b] + GP[320 + b] + GP[384 + b] + GP[448 + b]
                      + smem[OBF];
            dout[(size_t)b * (SS * FF) + (size_t)(SS - 1) * FF + blk] = gen;
        }
    }
    if (write_states && !ks) {
        size_t base = (size_t)BB * SS * FF;
        dout[base +               b * HH + uu] = h1v;
        dout[base + 1 * BB * HH + b * HH + uu] = c1;
        dout[base + 2 * BB * HH + b * HH + uu] = h2v;
        dout[base + 3 * BB * HH + b * HH + uu] = c2;
    }

    gsync(&s_sense);   // final barrier (even total -> replay-deterministic)
}

extern "C" void kernel_launch(void* const* d_in, const int* in_sizes, int n_in,
                              void* d_out, int out_size) {
    (void)in_sizes; (void)n_in;
    const float* x    = (const float*)d_in[0];
    const float* pg0  = (const float*)d_in[1];
    const float* h1   = (const float*)d_in[2];
    const float* c1   = (const float*)d_in[3];
    const float* h2   = (const float*)d_in[4];
    const float* c2   = (const float*)d_in[5];
    const float* Wfc1 = (const float*)d_in[6];
    const float* bfc1 = (const float*)d_in[7];
    const float* Wih1 = (const float*)d_in[8];
    const float* Whh1 = (const float*)d_in[9];
    const float* b1   = (const float*)d_in[10];
    const float* Wih2 = (const float*)d_in[11];
    const float* Whh2 = (const float*)d_in[12];
    const float* b2   = (const float*)d_in[13];
    const float* Wfc2 = (const float*)d_in[14];
    const float* bfc2 = (const float*)d_in[15];

    static int smem_set = 0;
    if (!smem_set) {
        cudaFuncSetAttribute(gencrnn_kernel,
                             cudaFuncAttributeMaxDynamicSharedMemorySize, SMEM_BYTES);
        smem_set = 1;
    }
    int write_states = (out_size >= BB * SS * FF + 4 * BB * HH) ? 1 : 0;
    gencrnn_kernel<<<NBLK, NTHR, SMEM_BYTES>>>(
        x, pg0, h1, c1, h2, c2, Wfc1, bfc1, Wih1, Whh1, b1,
        Wih2, Whh2, b2, Wfc2, bfc2, (float*)d_out, write_states);
}

// round 17
// speedup vs baseline: 1.5293x; 1.0417x over previous
#include <cuda_runtime.h>

// Persistent-kernel 2-layer LSTM recurrence (GenCRnn): B=64, S=2048, F=128, H=512.
// R17: double-buffered (depth-2) pipelined global loads in all dot loops.

#define NBLK 128
#define NTHR 512
#define BB   64
#define SS   2048
#define FF   128
#define HH   512

typedef unsigned long long ull;

// ---------------- global scratch (device BSS) --------------------------------
// Activation layout (float4 "b-innermost"): element (k, b) at float index
//   ((k>>2)*64 + b)*4 + (k&3)
__device__ __align__(16) float g_out[HH * BB];
__device__ __align__(16) float g_h1[2][HH * BB];
__device__ __align__(16) float g_h2[2][HH * BB];
__device__ unsigned g_count = 0;
__device__ unsigned g_sense = 0;

// ---------------- helpers ----------------------------------------------------
__device__ __forceinline__ ull ffma2(ull a, ull b, ull c) {
    ull d;
    asm("fma.rn.f32x2 %0, %1, %2, %3;" : "=l"(d) : "l"(a), "l"(b), "l"(c));
    return d;
}
__device__ __forceinline__ ull pk(float x, float y) {
    ull r;
    asm("mov.b64 %0, {%1, %2};" : "=l"(r) : "f"(x), "f"(y));
    return r;
}
__device__ __forceinline__ float psum(ull a) {
    unsigned lo, hi;
    asm("mov.b64 {%0, %1}, %2;" : "=r"(lo), "=r"(hi) : "l"(a));
    return __uint_as_float(lo) + __uint_as_float(hi);
}
__device__ __forceinline__ float sigm(float x) { return 1.0f / (1.0f + __expf(-x)); }

__device__ __forceinline__ unsigned atom_arrive(unsigned* p) {
    unsigned r;
    asm volatile("atom.acq_rel.gpu.global.add.u32 %0, [%1], 1;"
                 : "=r"(r) : "l"(p) : "memory");
    return r;
}
__device__ __forceinline__ unsigned ld_acq(unsigned* p) {
    unsigned r;
    asm volatile("ld.acquire.gpu.global.u32 %0, [%1];" : "=r"(r) : "l"(p) : "memory");
    return r;
}
__device__ __forceinline__ void st_rel(unsigned* p, unsigned v) {
    asm volatile("st.release.gpu.global.u32 [%0], %1;" :: "l"(p), "r"(v) : "memory");
}

// Sense-reversing grid barrier (L2-scope; all cross-block data is .cg).
// Even total barrier count per launch -> state returns to 0 -> replay-safe.
__device__ __forceinline__ void gsync(unsigned* s_sense) {
    __syncthreads();
    if (threadIdx.x == 0) {
        unsigned s = *s_sense;
        unsigned arr = atom_arrive(&g_count);
        if (arr == NBLK - 1) {
            g_count = 0;
            st_rel(&g_sense, s);
        } else {
            while (ld_acq(&g_sense) != s) { }
        }
        *s_sense = s ^ 1u;
    }
    __syncthreads();
}

// ---------------- pipelined dot helpers --------------------------------------
// acc[2g], acc[2g+1] accumulate lo/hi packed pairs for gate g.
// w layout: w[g*256 + k4]  (G=1 uses w[k4]).
template<int G>
__device__ __forceinline__ void dot8(const float4* __restrict__ v,
                                     const float4* __restrict__ w,
                                     ull* __restrict__ acc) {
#pragma unroll
    for (int j = 0; j < 8; j++) {
        ull vlo = pk(v[j].x, v[j].y), vhi = pk(v[j].z, v[j].w);
#pragma unroll
        for (int g = 0; g < G; g++) {
            float4 wv = w[g * 256 + j];
            acc[2 * g]     = ffma2(vlo, pk(wv.x, wv.y), acc[2 * g]);
            acc[2 * g + 1] = ffma2(vhi, pk(wv.z, wv.w), acc[2 * g + 1]);
        }
    }
}

// NB batches of 8 float4 (NB even, >=2). in = global base + b (stride 64 float4/k4).
// Depth-2 pipeline: batch i+1's loads fly while batch i computes.
template<int G, int NB>
__device__ __forceinline__ void dot_pipe(const float4* __restrict__ in,
                                         const float4* __restrict__ w,
                                         ull* __restrict__ acc) {
    float4 va[8], vb[8];
#pragma unroll
    for (int j = 0; j < 8; j++) va[j] = __ldcg(in + j * 64);
    int ofs = 0;
#pragma unroll 1
    for (int it = 0; it < (NB - 2) / 2; it++, ofs += 16) {
#pragma unroll
        for (int j = 0; j < 8; j++) vb[j] = __ldcg(in + (ofs + 8 + j) * 64);
        dot8<G>(va, w + ofs, acc);
#pragma unroll
        for (int j = 0; j < 8; j++) va[j] = __ldcg(in + (ofs + 16 + j) * 64);
        dot8<G>(vb, w + ofs + 8, acc);
    }
#pragma unroll
    for (int j = 0; j < 8; j++) vb[j] = __ldcg(in + (ofs + 8 + j) * 64);
    dot8<G>(va, w + ofs, acc);
    dot8<G>(vb, w + ofs + 8, acc);
}

// ---------------- SMEM layout (float offsets) --------------------------------
#define OW1  0        // LSTM1 rows: [4u][4gate][1024k] (k<512: Wih, else Whh)
#define OW2  16384    // LSTM2 rows
#define OWC  32768    // Wcomb: [4u][512k]
#define OWX  34816    // W_fc1 x-part rows: [4u][128f]
#define OWF  35328    // W_fc2 row `blk`: [512k]
#define OXS  35840    // x_t staging: 64 rows x 33 float4 = 8448 floats
#define OPP  44288    // K-split partials
#define OGP  45312    // gen partials: [8seg][64b]
#define OB1  45824
#define OB2  45840
#define OBC  45856
#define OBA  45860
#define OBF  45864
#define SMEM_FLOATS 45872
#define SMEM_BYTES  (SMEM_FLOATS * 4)

__global__ void __launch_bounds__(NTHR, 1)
gencrnn_kernel(
    const float* __restrict__ x,     const float* __restrict__ pg0,
    const float* __restrict__ h1in,  const float* __restrict__ c1in,
    const float* __restrict__ h2in,  const float* __restrict__ c2in,
    const float* __restrict__ Wfc1,  const float* __restrict__ bfc1,
    const float* __restrict__ Wih1,  const float* __restrict__ Whh1,
    const float* __restrict__ b1,
    const float* __restrict__ Wih2,  const float* __restrict__ Whh2,
    const float* __restrict__ b2,
    const float* __restrict__ Wfc2,  const float* __restrict__ bfc2,
    float* __restrict__ dout, int write_states)
{
    extern __shared__ float smem[];
    __shared__ unsigned s_sense;
    const int tid = threadIdx.x;
    const int blk = blockIdx.x;
    const int b   = tid & 63;
    const int u   = (tid >> 6) & 3;
    const int ks  = tid >> 8;
    const int uu  = blk * 4 + u;

    if (tid == 0) s_sense = 1u;

    float4* W1s = (float4*)(smem + OW1);
    float4* W2s = (float4*)(smem + OW2);
    float4* XS4 = (float4*)(smem + OXS);
    float*  PP  = smem + OPP;
    float*  GP  = smem + OGP;

    // ---------------- one-time weight load / precompute ----------------------
    for (int idx = tid; idx < 4096; idx += NTHR) {
        int lu = idx >> 10, g = (idx >> 8) & 3, i = idx & 255;
        int row = g * 512 + blk * 4 + lu;
        float4 v1 = (i < 128) ? ((const float4*)Wih1)[row * 128 + i]
                              : ((const float4*)Whh1)[row * 128 + (i - 128)];
        float4 v2 = (i < 128) ? ((const float4*)Wih2)[row * 128 + i]
                              : ((const float4*)Whh2)[row * 128 + (i - 128)];
        W1s[idx] = v1;
        W2s[idx] = v2;
    }
    for (int idx = tid; idx < 128; idx += NTHR) {
        int lu = idx >> 5, i = idx & 31;
        ((float4*)(smem + OWX))[idx] = ((const float4*)Wfc1)[(blk * 4 + lu) * 64 + i];
    }
    for (int idx = tid; idx < 512; idx += NTHR)
        smem[OWF + idx] = Wfc2[blk * 512 + idx];
    for (int idx = tid; idx < 2048; idx += NTHR) {
        int lu = idx >> 9, k = idx & 511;
        const float* wg = Wfc1 + (blk * 4 + lu) * 256 + 128;
        float s = 0.0f;
        for (int f = 0; f < 128; f++) s += wg[f] * Wfc2[f * 512 + k];
        smem[OWC + idx] = s;
    }
    if (tid < 16) {
        int lu = tid >> 2, g = tid & 3;
        smem[OB1 + tid] = b1[g * 512 + blk * 4 + lu];
        smem[OB2 + tid] = b2[g * 512 + blk * 4 + lu];
    }
    if (tid < 4) {
        const float* wg = Wfc1 + (blk * 4 + tid) * 256 + 128;
        float s = 0.0f;
        for (int f = 0; f < 128; f++) s += wg[f] * bfc2[f];
        smem[OBC + tid] = bfc1[blk * 4 + tid] + s;
        smem[OBA + tid] = bfc1[blk * 4 + tid];
    }
    if (tid == 0) smem[OBF] = bfc2[blk];

    float h1v = 0.0f, h2v = 0.0f, c1 = 0.0f, c2 = 0.0f;
    if (!ks) {
        h1v = h1in[b * HH + uu];
        h2v = h2in[b * HH + uu];
        c1  = c1in[b * HH + uu];
        c2  = c2in[b * HH + uu];
        __stcg(&g_h1[1][(blk * 64 + b) * 4 + u], h1v);
        __stcg(&g_h2[1][(blk * 64 + b) * 4 + u], h2v);
    }

    gsync(&s_sense);   // barrier #1

    const float4* wxr = (const float4*)(smem + OWX) + u * 32;
    const float4* wcr = (const float4*)(smem + OWC) + u * 128;
    const float4* wf4 = (const float4*)(smem + OWF);

    for (int t = 0; t < SS; t++) {
        const int w  = t & 1;
        const int rb = w ^ 1;
        const float4* h2prev = (const float4*)g_h2[rb];

        // ================= phase A ========================================
#pragma unroll
        for (int it = 0; it < 4; it++) {
            int g2 = it * NTHR + tid;
            int bb = g2 >> 5, i2 = g2 & 31;
            XS4[bb * 33 + i2] =
                ((const float4*)x)[(size_t)bb * (SS * 32) + (size_t)t * 32 + i2];
        }
        __syncthreads();

        ull acc[2] = {0ull, 0ull};
        float extra = 0.0f;
        if (t > 0) {                                  // h2prev · Wcomb (48/80 split)
            if (!ks) dot_pipe<1, 6>(h2prev + b, wcr, acc);
            else     dot_pipe<1, 10>(h2prev + 48 * 64 + b, wcr + 48, acc);
        } else if (ks) {                              // t==0: prev_gen0 path
            const float* pgr = pg0 + b * FF;
            const float* wgr = Wfc1 + uu * 256 + 128;
            float s = 0.0f;
            for (int f = 0; f < 128; f++) s += pgr[f] * wgr[f];
            extra = s;
        }
        if (!ks) {                                    // x · W_fc1(x-part), smem
            const float4* xr = XS4 + b * 33;
#pragma unroll 8
            for (int i = 0; i < 32; i++) {
                float4 v = xr[i], wv = wxr[i];
                acc[0] = ffma2(pk(v.x, v.y), pk(wv.x, wv.y), acc[0]);
                acc[1] = ffma2(pk(v.z, v.w), pk(wv.z, wv.w), acc[1]);
            }
        }
        float part = psum(acc[0]) + psum(acc[1]) + extra;

        // gen_{t-1} partial: 8-way split over (u, ks)
        float gp = 0.0f;
        if (t > 0) {
            const int seg = u * 2 + ks;
            ull q[2] = {0ull, 0ull};
            dot_pipe<1, 2>(h2prev + seg * 16 * 64 + b, wf4 + seg * 16, q);
            gp = psum(q[0]) + psum(q[1]);
        }
        if (ks) PP[u * 64 + b] = part;
        GP[(u * 2 + ks) * 64 + b] = gp;
        __syncthreads();
        if (!ks) {
            float acc2 = part + PP[u * 64 + b] + (t == 0 ? smem[OBA + u] : smem[OBC + u]);
            __stcg(&g_out[(blk * 64 + b) * 4 + u], fmaxf(acc2, 0.0f));
        }
        if (t > 0 && tid < 64) {
            float gen = GP[b] + GP[64 + b] + GP[128 + b] + GP[192 + b]
                      + GP[256 + b] + GP[320 + b] + GP[384 + b] + GP[448 + b]
                      + smem[OBF];
            dout[(size_t)b * (SS * FF) + (size_t)(t - 1) * FF + blk] = gen;
        }
        gsync(&s_sense);

        // ================= phase B: LSTM1 =================================
        {
            ull a[8];
#pragma unroll
            for (int g = 0; g < 8; g++) a[g] = 0ull;
            const float4* in = ks ? (const float4*)g_h1[rb] : (const float4*)g_out;
            dot_pipe<4, 16>(in + b, (const float4*)(smem + OW1) + u * 1024 + ks * 128, a);
            if (ks) {
                *(float4*)&PP[(u * 64 + b) * 4] =
                    make_float4(psum(a[0]) + psum(a[1]), psum(a[2]) + psum(a[3]),
                                psum(a[4]) + psum(a[5]), psum(a[6]) + psum(a[7]));
            }
            __syncthreads();
            if (!ks) {
                float4 q = *(const float4*)&PP[(u * 64 + b) * 4];
                float ig = sigm(psum(a[0]) + psum(a[1]) + q.x + smem[OB1 + u * 4 + 0]);
                float fg = sigm(psum(a[2]) + psum(a[3]) + q.y + smem[OB1 + u * 4 + 1]);
                float gg = tanhf(psum(a[4]) + psum(a[5]) + q.z + smem[OB1 + u * 4 + 2]);
                float og = sigm(psum(a[6]) + psum(a[7]) + q.w + smem[OB1 + u * 4 + 3]);
                c1 = fg * c1 + ig * gg;
                h1v = og * tanhf(c1);
                __stcg(&g_h1[w][(blk * 64 + b) * 4 + u], h1v);
            }
            gsync(&s_sense);
        }

        // ================= phase C: LSTM2 =================================
        {
            ull a[8];
#pragma unroll
            for (int g = 0; g < 8; g++) a[g] = 0ull;
            const float4* in = ks ? (const float4*)g_h2[rb] : (const float4*)g_h1[w];
            dot_pipe<4, 16>(in + b, (const float4*)(smem + OW2) + u * 1024 + ks * 128, a);
            if (ks) {
                *(float4*)&PP[(u * 64 + b) * 4] =
                    make_float4(psum(a[0]) + psum(a[1]), psum(a[2]) + psum(a[3]),
                                psum(a[4]) + psum(a[5]), psum(a[6]) + psum(a[7]));
            }
            __syncthreads();
            if (!ks) {
                float4 q = *(const float4*)&PP[(u * 64 + b) * 4];
                float ig = sigm(psum(a[0]) + psum(a[1]) + q.x + smem[OB2 + u * 4 + 0]);
                float fg = sigm(psum(a[2]) + psum(a[3]) + q.y + smem[OB2 + u * 4 + 1]);
                float gg = tanhf(psum(a[4]) + psum(a[5]) + q.z + smem[OB2 + u * 4 + 2]);
                float og = sigm(psum(a[6]) + psum(a[7]) + q.w + smem[OB2 + u * 4 + 3]);
                c2 = fg * c2 + ig * gg;
                h2v = og * tanhf(c2);
                __stcg(&g_h2[w][(blk * 64 + b) * 4 + u], h2v);
            }
            gsync(&s_sense);
        }
    }

    // -------- tail: gen_{S-1} from final h2 (buffer 1) ----------------------
    {
        const float4* h2f = (const float4*)g_h2[1];
        const int seg = u * 2 + ks;
        ull q[2] = {0ull, 0ull};
        dot_pipe<1, 2>(h2f + seg * 16 * 64 + b, wf4 + seg * 16, q);
        GP[seg * 64 + b] = psum(q[0]) + psum(q[1]);
        __syncthreads();
        if (tid < 64) {
            float gen = GP[b] + GP[64 + b] + GP[128 + b] + GP[192 + b]
                      + GP[256 + b] + GP[320 + b] + GP[384 + b] + GP[448 + b]
                      + smem[OBF];
            dout[(size_t)b * (SS * FF) + (size_t)(SS - 1) * FF + blk] = gen;
        }
    }
    if (write_states && !ks) {
        size_t base = (size_t)BB * SS * FF;
        dout[base +               b * HH + uu] = h1v;
        dout[base + 1 * BB * HH + b * HH + uu] = c1;
        dout[base + 2 * BB * HH + b * HH + uu] = h2v;
        dout[base + 3 * BB * HH + b * HH + uu] = c2;
    }

    gsync(&s_sense);   // final barrier (even total -> replay-deterministic)
}

extern "C" void kernel_launch(void* const* d_in, const int* in_sizes, int n_in,
                              void* d_out, int out_size) {
    (void)in_sizes; (void)n_in;
    const float* x    = (const float*)d_in[0];
    const float* pg0  = (const float*)d_in[1];
    const float* h1   = (const float*)d_in[2];
    const float* c1   = (const float*)d_in[3];
    const float* h2   = (const float*)d_in[4];
    const float* c2   = (const float*)d_in[5];
    const float* Wfc1 = (const float*)d_in[6];
    const float* bfc1 = (const float*)d_in[7];
    const float* Wih1 = (const float*)d_in[8];
    const float* Whh1 = (const float*)d_in[9];
    const float* b1   = (const float*)d_in[10];
    const float* Wih2 = (const float*)d_in[11];
    const float* Whh2 = (const float*)d_in[12];
    const float* b2   = (const float*)d_in[13];
    const float* Wfc2 = (const float*)d_in[14];
    const float* bfc2 = (const float*)d_in[15];

    static int smem_set = 0;
    if (!smem_set) {
        cudaFuncSetAttribute(gencrnn_kernel,
                             cudaFuncAttributeMaxDynamicSharedMemorySize, SMEM_BYTES);
        smem_set = 1;
    }
    int write_states = (out_size >= BB * SS * FF + 4 * BB * HH) ? 1 : 0;
    gencrnn_kernel<<<NBLK, NTHR, SMEM_BYTES>>>(
        x, pg0, h1, c1, h2, c2, Wfc1, bfc1, Wih1, Whh1, b1,
        Wih2, Whh2, b2, Wfc2, bfc2, (float*)d_out, write_states);
}